// round 5
// baseline (speedup 1.0000x reference)
#include <cuda_runtime.h>
#include <cstdint>

// Depthwise1d: out[n,c,o] = sum_i x[n,c,i] * W[c,o,i] + b[c,o]
// N=4096, C=256, K=64, O=128, fp32.
//
// R4: scalar FFMA2 (fma.rn.f32x2), f32x2 lane = ROW PAIR.
//  - x transposed in smem (XT[k][row]) -> conflict-free row-pair LDS.64
//  - W read via broadcast LDS.128 (1 wavefront serves 4 k-steps), dup to (w,w)
//  - warp = 128 rows x 16 cols; thread = 4 rows x 16 cols (32 u64 accs)
// Cuts smem crossbar demand from 1.5x to 0.5x of FMA-pipe demand.

#define N_TOT   4096
#define C_TOT   256
#define K_IN    64
#define O_OUT   128
#define TILE_M  128
#define THREADS 256
#define XTS     130      // XT row stride in floats (k-major rows of 128 rows + pad)

// smem layout (bytes):
#define SM_BIAS  0                     // 128 floats = 512 B
#define SM_XT    512                   // 64 * 130 * 4 = 33280 B
#define SM_W     (SM_XT + 64 * XTS * 4)   // 33792, 16B aligned
#define SM_TOTAL (SM_W + 128 * 64 * 4)    // 33792 + 32768 = 66560 B

__device__ __forceinline__ void ffma2(unsigned long long& d,
                                      unsigned long long a,
                                      unsigned long long b) {
    asm("fma.rn.f32x2 %0, %1, %2, %0;" : "+l"(d) : "l"(a), "l"(b));
}
__device__ __forceinline__ unsigned long long dup2(float w) {
    unsigned long long r;
    asm("mov.b64 %0, {%1, %1};" : "=l"(r) : "f"(w));
    return r;
}
__device__ __forceinline__ float2 unpack2(unsigned long long v) {
    float2 f;
    asm("mov.b64 {%0, %1}, %2;" : "=f"(f.x), "=f"(f.y) : "l"(v));
    return f;
}

__global__ __launch_bounds__(THREADS, 2)
void dw1d_kernel(const float* __restrict__ x,
                 const float* __restrict__ W,
                 const float* __restrict__ b,
                 float* __restrict__ out) {
    extern __shared__ float smem[];
    float* bias_sh = smem + SM_BIAS / 4;
    float* XT      = smem + SM_XT / 4;    // [k][row], stride XTS
    float* Wsh     = smem + SM_W / 4;     // [o][k], stride 64

    const int t   = threadIdx.x;
    const int wid = t >> 5;
    const int lid = t & 31;
    const int n0  = blockIdx.x * TILE_M;
    const int c   = blockIdx.y;

    if (t < O_OUT) bias_sh[t] = b[c * O_OUT + t];

    // ---- Stage x: transpose [row][k] -> XT[k][row], row-pairs packed ----
    // thread: ku = t&15 (float4 along k), a0 = t>>4 (row-pair), 4 j-iters.
    {
        const int ku = t & 15;
        const int a0 = t >> 4;
#pragma unroll
        for (int j = 0; j < 4; ++j) {
            int a = a0 + 16 * j;               // row pair index 0..63
            const float* p0 = x + ((size_t)(n0 + 2 * a) * C_TOT + c) * K_IN + 4 * ku;
            const float* p1 = p0 + (size_t)C_TOT * K_IN;
            float4 va = *(const float4*)p0;    // row 2a,   k=4ku..4ku+3
            float4 vb = *(const float4*)p1;    // row 2a+1
            float2* dst0 = (float2*)&XT[(4 * ku + 0) * XTS + 2 * a];
            float2* dst1 = (float2*)&XT[(4 * ku + 1) * XTS + 2 * a];
            float2* dst2 = (float2*)&XT[(4 * ku + 2) * XTS + 2 * a];
            float2* dst3 = (float2*)&XT[(4 * ku + 3) * XTS + 2 * a];
            *dst0 = make_float2(va.x, vb.x);
            *dst1 = make_float2(va.y, vb.y);
            *dst2 = make_float2(va.z, vb.z);
            *dst3 = make_float2(va.w, vb.w);
        }
    }
    // ---- Stage W: [o][k] stride 64, float4, coalesced & conflict-free ----
    {
        const float* wbase = W + (size_t)c * O_OUT * K_IN;
#pragma unroll
        for (int j = 0; j < 8; ++j) {
            int idx = t + THREADS * j;         // 0..2047
            int o  = idx >> 4;                 // 0..127
            int k4 = idx & 15;                 // 0..15
            float4 v = *(const float4*)(wbase + (size_t)o * K_IN + 4 * k4);
            *(float4*)&Wsh[o * K_IN + 4 * k4] = v;
        }
    }
    __syncthreads();

    // ---- Compute: thread = rows {4l..4l+3} x cols {16*wid..+15} ----
    unsigned long long acc[2][16];             // [row-pair][col]
#pragma unroll
    for (int rp = 0; rp < 2; ++rp)
#pragma unroll
        for (int cc = 0; cc < 16; ++cc)
            acc[rp][cc] = 0ULL;

    const int colbase = wid * 16;
    const int rbase   = 4 * lid;               // row base (pairs at rbase, rbase+2)

#pragma unroll 2
    for (int k4 = 0; k4 < K_IN / 4; ++k4) {
        unsigned long long xv[4][2];           // [kk][row-pair]
#pragma unroll
        for (int kk = 0; kk < 4; ++kk) {
            const float* row = &XT[(4 * k4 + kk) * XTS + rbase];
            xv[kk][0] = *(const unsigned long long*)(row);
            xv[kk][1] = *(const unsigned long long*)(row + 2);
        }
#pragma unroll
        for (int cc = 0; cc < 16; ++cc) {
            // broadcast: all 32 lanes same address -> 1 wavefront
            float4 wq = *(const float4*)&Wsh[(colbase + cc) * K_IN + 4 * k4];
            unsigned long long w0 = dup2(wq.x);
            unsigned long long w1 = dup2(wq.y);
            unsigned long long w2 = dup2(wq.z);
            unsigned long long w3 = dup2(wq.w);
            ffma2(acc[0][cc], xv[0][0], w0);
            ffma2(acc[1][cc], xv[0][1], w0);
            ffma2(acc[0][cc], xv[1][0], w1);
            ffma2(acc[1][cc], xv[1][1], w1);
            ffma2(acc[0][cc], xv[2][0], w2);
            ffma2(acc[1][cc], xv[2][1], w2);
            ffma2(acc[0][cc], xv[3][0], w3);
            ffma2(acc[1][cc], xv[3][1], w3);
        }
    }

    // ---- Epilogue: add bias, store 4 rows x 16 contiguous cols ----
    float bb[16];
#pragma unroll
    for (int cc = 0; cc < 16; ++cc)
        bb[cc] = bias_sh[colbase + cc];        // broadcast LDS

#pragma unroll
    for (int i = 0; i < 4; ++i) {
        const int rp  = i >> 1;
        const int sel = i & 1;
        const int n   = n0 + rbase + 2 * rp + sel;
        float* orow = out + ((size_t)n * C_TOT + c) * O_OUT + colbase;
#pragma unroll
        for (int g = 0; g < 4; ++g) {
            float4 v;
            float2 f0 = unpack2(acc[rp][4 * g + 0]);
            float2 f1 = unpack2(acc[rp][4 * g + 1]);
            float2 f2 = unpack2(acc[rp][4 * g + 2]);
            float2 f3 = unpack2(acc[rp][4 * g + 3]);
            v.x = (sel ? f0.y : f0.x) + bb[4 * g + 0];
            v.y = (sel ? f1.y : f1.x) + bb[4 * g + 1];
            v.z = (sel ? f2.y : f2.x) + bb[4 * g + 2];
            v.w = (sel ? f3.y : f3.x) + bb[4 * g + 3];
            *(float4*)&orow[4 * g] = v;
        }
    }
}

extern "C" void kernel_launch(void* const* d_in, const int* in_sizes, int n_in,
                              void* d_out, int out_size) {
    const float* x = (const float*)d_in[0];
    const float* W = (const float*)d_in[1];
    const float* b = (const float*)d_in[2];
    float* out = (float*)d_out;

    cudaFuncSetAttribute(dw1d_kernel,
                         cudaFuncAttributeMaxDynamicSharedMemorySize, SM_TOTAL);

    dim3 grid(N_TOT / TILE_M, C_TOT);
    dw1d_kernel<<<grid, THREADS, SM_TOTAL>>>(x, W, b, out);
}